// round 2
// baseline (speedup 1.0000x reference)
#include <cuda_runtime.h>

// LogSparseAttention — B=2, L=S=2048, H=8, E=D=64, fp32.
// Key insight: with win_len==sub_len==2048, log_l=11, the log-sparse mask has
// at most 22 nonzero columns per row:
//   l < 22  : causal 0..l
//   l >= 22 : contiguous [l-10, l]  +  points { l-10-2^k : k=0..10, >=0 }
// One warp per (b,h,l) row; lane c owns column c.

#define BB 2
#define LL 2048
#define SS 2048
#define HH 8
#define EE 64
#define DD 64
#define WARPS_PER_BLOCK 8

__global__ __launch_bounds__(WARPS_PER_BLOCK * 32)
void logsparse_attn_kernel(const float* __restrict__ q,
                           const float* __restrict__ k,
                           const float* __restrict__ v,
                           float* __restrict__ out)
{
    const int warpId = threadIdx.x >> 5;
    const int lane   = threadIdx.x & 31;
    const int r = blockIdx.x * WARPS_PER_BLOCK + warpId;   // 0 .. B*H*L-1
    // r -> (b, h, l); l fastest so adjacent warps share K/V window (L2 reuse)
    const int b   = r / (HH * LL);
    const int rem = r - b * (HH * LL);
    const int h   = rem / LL;
    const int l   = rem - h * LL;

    // ---- column assignment for this lane ----
    int  j = 0;
    bool active = false;
    if (l < 22) {
        if (lane <= l) { j = lane; active = true; }       // causal row, <=22 cols
    } else {
        if (lane <= 10) {                                  // contiguous [l-10, l]
            j = l - 10 + lane; active = true;
        } else if (lane <= 21) {                           // log points
            int jj = l - 10 - (1 << (lane - 11));
            if (jj >= 0) { j = jj; active = true; }
        }
    }

    // ---- stage Q row in shared (broadcast reads, conflict-free) ----
    __shared__ float qs[WARPS_PER_BLOCK][EE];
    {
        const float* qp = q + (((size_t)b * LL + l) * HH + h) * EE;
        qs[warpId][lane]      = qp[lane];
        qs[warpId][lane + 32] = qp[lane + 32];
    }
    __syncwarp();

    // ---- per-lane Q.K dot over its column ----
    float s = 0.0f;
    if (active) {
        const float4* kp = reinterpret_cast<const float4*>(
            k + (((size_t)b * SS + j) * HH + h) * EE);
        const float4* qp4 = reinterpret_cast<const float4*>(qs[warpId]);
        #pragma unroll
        for (int e = 0; e < EE / 4; e++) {
            const float4 k4 = kp[e];
            const float4 q4 = qp4[e];
            s += q4.x * k4.x + q4.y * k4.y + q4.z * k4.z + q4.w * k4.w;
        }
    }
    s *= 0.125f;   // 1/sqrt(E)

    // ---- warp softmax over active lanes ----
    float m = active ? s : -1e30f;
    #pragma unroll
    for (int off = 16; off; off >>= 1)
        m = fmaxf(m, __shfl_xor_sync(0xffffffffu, m, off));
    float p = active ? __expf(s - m) : 0.0f;
    float denom = p;
    #pragma unroll
    for (int off = 16; off; off >>= 1)
        denom += __shfl_xor_sync(0xffffffffu, denom, off);
    p /= denom;

    // ---- AV: each lane accumulates 2 output dims over <=22 columns ----
    float2 acc = make_float2(0.0f, 0.0f);
    const float2* v2 = reinterpret_cast<const float2*>(v);
    #pragma unroll
    for (int c = 0; c < 22; c++) {
        const float pc = __shfl_sync(0xffffffffu, p, c);
        const int   jc = __shfl_sync(0xffffffffu, j, c);
        if (pc > 0.0f) {   // warp-uniform skip of masked/out-of-range columns
            const float2 val =
                v2[(((size_t)b * SS + jc) * HH + h) * (DD / 2) + lane];
            acc.x += pc * val.x;
            acc.y += pc * val.y;
        }
    }

    float2* o2 = reinterpret_cast<float2*>(out);
    o2[(((size_t)b * LL + l) * HH + h) * (DD / 2) + lane] = acc;
}

extern "C" void kernel_launch(void* const* d_in, const int* in_sizes, int n_in,
                              void* d_out, int out_size)
{
    const float* q = (const float*)d_in[0];
    const float* k = (const float*)d_in[1];
    const float* v = (const float*)d_in[2];
    float* out = (float*)d_out;

    const int total_rows = BB * HH * LL;                   // 32768 warps
    const int blocks = total_rows / WARPS_PER_BLOCK;       // 4096
    logsparse_attn_kernel<<<blocks, WARPS_PER_BLOCK * 32>>>(q, k, v, out);
}

// round 4
// speedup vs baseline: 1.8493x; 1.8493x over previous
#include <cuda_runtime.h>

// LogSparseAttention — B=2, L=S=2048, H=8, E=D=64, fp32.
// With win_len==sub_len==2048, log_l=11, each row attends to <=22 columns:
//   l < 22  : causal 0..l
//   l >= 22 : contiguous [l-10, l]  +  points { l-10-2^k : k=0..10, >=0 }
// One warp per (b,h,l) row. Columns processed in PAIRS: lower 16 lanes own
// the even column, upper 16 lanes the odd column, so every K/V load is a
// single coalesced 256B row per half-warp (2x256B per LDG.128).

#define BB 2
#define LL 2048
#define SS 2048
#define HH 8
#define EE 64
#define DD 64
#define WARPS_PER_BLOCK 8
#define FULL 0xffffffffu

// column index for row l, slot c (0..21); -1 if inactive
__device__ __forceinline__ int col_index(int l, int c) {
    if (l < 22) return (c <= l) ? c : -1;
    if (c <= 10) return l - 10 + c;
    const int j = l - 10 - (1 << (c - 11));
    return (j >= 0) ? j : -1;
}

__global__ __launch_bounds__(WARPS_PER_BLOCK * 32)
void logsparse_attn_kernel(const float* __restrict__ q,
                           const float* __restrict__ k,
                           const float* __restrict__ v,
                           float* __restrict__ out)
{
    const int warpId = threadIdx.x >> 5;
    const int lane   = threadIdx.x & 31;
    const int half   = lane >> 4;          // 0: even column of pair, 1: odd
    const int hl     = lane & 15;          // position within half
    const int r = blockIdx.x * WARPS_PER_BLOCK + warpId;   // 0 .. B*H*L-1
    const int b   = r / (HH * LL);
    const int rem = r - b * (HH * LL);
    const int h   = rem / LL;
    const int l   = rem - h * LL;

    // Q fragment: lane holds q[hl*4 .. hl*4+3] (duplicated across halves)
    const float* qrow = q + (((size_t)b * LL + l) * HH + h) * EE;
    const float4 q4 = reinterpret_cast<const float4*>(qrow)[hl];

    const float* kbase = k + ((size_t)b * SS * HH + h) * EE;  // + j*HH*EE
    const float* vbase = v + ((size_t)b * SS * HH + h) * EE;

    // ---- QK: 11 column pairs; each LDG.128 fetches two full K rows ----
    float s = -1e30f;
    #pragma unroll
    for (int t = 0; t < 11; t++) {
        const int c0 = 2 * t;
        const int c1 = 2 * t + 1;
        const int jc0 = col_index(l, c0);
        const int jc1 = col_index(l, c1);
        const int jme = half ? jc1 : jc0;

        float partial = 0.0f;
        if (jme >= 0) {
            const float4 k4 = reinterpret_cast<const float4*>(
                kbase + (size_t)jme * (HH * EE))[hl];
            partial = q4.x * k4.x + q4.y * k4.y + q4.z * k4.z + q4.w * k4.w;
        }
        // reduce within each 16-lane half (both columns at once)
        #pragma unroll
        for (int off = 8; off; off >>= 1)
            partial += __shfl_xor_sync(FULL, partial, off);
        const float other = __shfl_xor_sync(FULL, partial, 16);
        // at any lane: value of even col = (half ? other : partial), odd col swaps
        const float sc0 = half ? other : partial;
        const float sc1 = half ? partial : other;
        if (lane == c0 && jc0 >= 0) s = sc0;
        if (lane == c1 && jc1 >= 0) s = sc1;
    }
    s *= 0.125f;   // 1/sqrt(E); inactive lanes stay at ~-1e29

    // ---- warp softmax over the 22 column slots ----
    float m = s;
    #pragma unroll
    for (int off = 16; off; off >>= 1)
        m = fmaxf(m, __shfl_xor_sync(FULL, m, off));
    float p = __expf(s - m);               // underflows to exactly 0 when inactive
    float denom = p;
    #pragma unroll
    for (int off = 16; off; off >>= 1)
        denom += __shfl_xor_sync(FULL, denom, off);
    p /= denom;

    // ---- AV: lower half accumulates even columns, upper half odd columns ----
    float4 acc = make_float4(0.0f, 0.0f, 0.0f, 0.0f);
    #pragma unroll
    for (int t = 0; t < 11; t++) {
        const int c = 2 * t + half;
        const float pc_even = __shfl_sync(FULL, p, 2 * t);
        const float pc_odd  = __shfl_sync(FULL, p, 2 * t + 1);
        const float pc = half ? pc_odd : pc_even;
        if (pc != 0.0f) {                  // masked/out-of-range columns have p==0
            const int jc = col_index(l, c);
            const float4 v4 = reinterpret_cast<const float4*>(
                vbase + (size_t)jc * (HH * EE))[hl];
            acc.x += pc * v4.x;
            acc.y += pc * v4.y;
            acc.z += pc * v4.z;
            acc.w += pc * v4.w;
        }
    }
    // fold the two halves' contributions
    acc.x += __shfl_xor_sync(FULL, acc.x, 16);
    acc.y += __shfl_xor_sync(FULL, acc.y, 16);
    acc.z += __shfl_xor_sync(FULL, acc.z, 16);
    acc.w += __shfl_xor_sync(FULL, acc.w, 16);

    if (half == 0) {
        float4* orow = reinterpret_cast<float4*>(
            out + (((size_t)b * LL + l) * HH + h) * DD);
        orow[hl] = acc;
    }
}

extern "C" void kernel_launch(void* const* d_in, const int* in_sizes, int n_in,
                              void* d_out, int out_size)
{
    const float* q = (const float*)d_in[0];
    const float* k = (const float*)d_in[1];
    const float* v = (const float*)d_in[2];
    float* out = (float*)d_out;

    const int total_rows = BB * HH * LL;                   // 32768 warps
    const int blocks = total_rows / WARPS_PER_BLOCK;       // 4096
    logsparse_attn_kernel<<<blocks, WARPS_PER_BLOCK * 32>>>(q, k, v, out);
}

// round 5
// speedup vs baseline: 1.8722x; 1.0124x over previous
#include <cuda_runtime.h>

// LogSparseAttention — B=2, L=S=2048, H=8, E=D=64, fp32.
// log_l=11 => each row attends to <=22 columns:
//   l < 22  : causal 0..l
//   l >= 22 : contiguous [l-10, l]  +  points { l-10-2^k : k=0..10, >=0 }
// One warp per (b,h,l) row.
//   QK: 6 rounds x 4 columns, 8 lanes per column (each lane dots 8 contiguous
//       elements) -> 3 reduce shuffles + 1 park shuffle per round.
//   AV: 11 rounds x 2 columns, 16 lanes per column (coalesced 256B rows).
// All loads unconditional: inactive columns clamp to row 0 and are zeroed by
// p==0 exactly (exp underflow), matching the reference mask semantics.

#define BB 2
#define LL 2048
#define SS 2048
#define HH 8
#define EE 64
#define DD 64
#define WARPS_PER_BLOCK 8
#define FULL 0xffffffffu
#define ROW_STRIDE (HH * EE)   // 512 floats between consecutive seq positions

__global__ __launch_bounds__(WARPS_PER_BLOCK * 32)
void logsparse_attn_kernel(const float* __restrict__ q,
                           const float* __restrict__ k,
                           const float* __restrict__ v,
                           float* __restrict__ out)
{
    const int warpId = threadIdx.x >> 5;
    const int lane   = threadIdx.x & 31;
    const int r = blockIdx.x * WARPS_PER_BLOCK + warpId;   // 0 .. B*H*L-1
    const int b   = r / (HH * LL);
    const int rem = r - b * (HH * LL);
    const int h   = rem / LL;
    const int l   = rem - h * LL;

    // ---- parked column index: lane c holds column for slot c (0..21), -1 inactive
    int jpark = -1;
    if (l < 22) {
        if (lane <= l) jpark = lane;
    } else if (lane <= 10) {
        jpark = l - 10 + lane;
    } else if (lane <= 21) {
        const int t = l - 10 - (1 << (lane - 11));
        if (t >= 0) jpark = t;
    }

    const int g  = lane >> 3;   // column group within a QK round (0..3)
    const int gl = lane & 7;    // lane within group: owns elements gl*8..gl*8+7

    // Q fragment (each lane 8 contiguous elements; broadcast across groups)
    const float* qrow = q + (((size_t)b * LL + l) * HH + h) * EE;
    const float4 qa = reinterpret_cast<const float4*>(qrow)[gl * 2];
    const float4 qb = reinterpret_cast<const float4*>(qrow)[gl * 2 + 1];

    const float* kbase = k + ((size_t)b * SS * HH + h) * EE;
    const float* vbase = v + ((size_t)b * SS * HH + h) * EE;

    // ---- QK: 6 rounds x 4 columns (slots 0..23; 22,23 always inactive) ----
    float s = -1e30f;
    #pragma unroll
    for (int rr = 0; rr < 6; rr++) {
        const int slot = 4 * rr + g;                         // this lane's column slot
        const int jl   = __shfl_sync(FULL, jpark, slot);     // lanes 22/23 hold -1
        const int jc   = max(jl, 0);                         // clamp: load row 0 if inactive
        const float4* kp = reinterpret_cast<const float4*>(
            kbase + (size_t)jc * ROW_STRIDE);
        const float4 ka = kp[gl * 2];
        const float4 kb = kp[gl * 2 + 1];
        float partial = qa.x * ka.x + qa.y * ka.y + qa.z * ka.z + qa.w * ka.w
                      + qb.x * kb.x + qb.y * kb.y + qb.z * kb.z + qb.w * kb.w;
        partial += __shfl_xor_sync(FULL, partial, 4);
        partial += __shfl_xor_sync(FULL, partial, 2);
        partial += __shfl_xor_sync(FULL, partial, 1);
        // park at lane == slot: lane 4rr+d takes group d's value (lane 8d)
        const float got = __shfl_sync(FULL, partial, ((lane - 4 * rr) & 3) << 3);
        if ((lane >> 2) == rr && jpark >= 0) s = got * 0.125f;   // 1/sqrt(E)
    }

    // ---- warp softmax over the 22 column slots (inactive lanes -> p = 0) ----
    float m = s;
    #pragma unroll
    for (int off = 16; off; off >>= 1)
        m = fmaxf(m, __shfl_xor_sync(FULL, m, off));
    float p = __expf(s - m);           // exact 0 on inactive lanes
    float denom = p;
    #pragma unroll
    for (int off = 16; off; off >>= 1)
        denom += __shfl_xor_sync(FULL, denom, off);
    p = __fdividef(p, denom);

    // ---- AV: lower half = even columns, upper half = odd; branch-free ----
    const int half = lane >> 4;
    const int hl   = lane & 15;
    float4 acc = make_float4(0.0f, 0.0f, 0.0f, 0.0f);
    #pragma unroll
    for (int t = 0; t < 11; t++) {
        const int   cs = 2 * t + half;
        const float pc = __shfl_sync(FULL, p, cs);
        const int   jv = __shfl_sync(FULL, jpark, cs);
        const int   jc = max(jv, 0);                 // pc==0 annihilates clamped rows
        const float4 v4 = reinterpret_cast<const float4*>(
            vbase + (size_t)jc * ROW_STRIDE)[hl];
        acc.x = fmaf(pc, v4.x, acc.x);
        acc.y = fmaf(pc, v4.y, acc.y);
        acc.z = fmaf(pc, v4.z, acc.z);
        acc.w = fmaf(pc, v4.w, acc.w);
    }
    // fold the two halves
    acc.x += __shfl_xor_sync(FULL, acc.x, 16);
    acc.y += __shfl_xor_sync(FULL, acc.y, 16);
    acc.z += __shfl_xor_sync(FULL, acc.z, 16);
    acc.w += __shfl_xor_sync(FULL, acc.w, 16);

    if (half == 0) {
        float4* orow = reinterpret_cast<float4*>(
            out + (((size_t)b * LL + l) * HH + h) * DD);
        orow[hl] = acc;
    }
}

extern "C" void kernel_launch(void* const* d_in, const int* in_sizes, int n_in,
                              void* d_out, int out_size)
{
    const float* q = (const float*)d_in[0];
    const float* k = (const float*)d_in[1];
    const float* v = (const float*)d_in[2];
    float* out = (float*)d_out;

    const int total_rows = BB * HH * LL;                   // 32768 warps
    const int blocks = total_rows / WARPS_PER_BLOCK;       // 4096
    logsparse_attn_kernel<<<blocks, WARPS_PER_BLOCK * 32>>>(q, k, v, out);
}

// round 6
// speedup vs baseline: 2.0731x; 1.1073x over previous
#include <cuda_runtime.h>

// LogSparseAttention — B=2, L=S=2048, H=8, E=D=64, fp32.
// log_l=11 => each row attends to <=22 columns:
//   l < 22  : causal 0..l
//   l >= 22 : contiguous [l-10, l]  +  points { l-10-2^k : k=0..10, >=0 }
// One warp per (b,h,l) row.
// QK and AV both use the PAIR pattern: lower 16 lanes own the even column of
// the pair, upper 16 lanes the odd one; every LDG.128 fetches two complete
// 256B K/V rows (4 L1 wavefronts). Branch-free: inactive columns clamp to
// row 0 and are annihilated exactly by p==0 (exp underflow), matching the
// reference's -1e9 mask semantics.

#define BB 2
#define LL 2048
#define SS 2048
#define HH 8
#define EE 64
#define DD 64
#define WARPS_PER_BLOCK 8
#define FULL 0xffffffffu
#define ROW_STRIDE (HH * EE)   // 512 floats between consecutive seq positions

__global__ __launch_bounds__(WARPS_PER_BLOCK * 32)
void logsparse_attn_kernel(const float* __restrict__ q,
                           const float* __restrict__ k,
                           const float* __restrict__ v,
                           float* __restrict__ out)
{
    const int warpId = threadIdx.x >> 5;
    const int lane   = threadIdx.x & 31;
    const int half   = lane >> 4;          // 0: even column of pair, 1: odd
    const int hl     = lane & 15;          // position within half (owns 16B chunk hl)
    const int r = blockIdx.x * WARPS_PER_BLOCK + warpId;   // 0 .. B*H*L-1
    const int b   = r / (HH * LL);
    const int rem = r - b * (HH * LL);
    const int h   = rem / LL;
    const int l   = rem - h * LL;

    // parked column index: lane c holds column for slot c (0..21), -1 inactive
    int jpark = -1;
    if (l < 22) {
        if (lane <= l) jpark = lane;
    } else if (lane <= 10) {
        jpark = l - 10 + lane;
    } else if (lane <= 21) {
        const int t = l - 10 - (1 << (lane - 11));
        if (t >= 0) jpark = t;
    }
    const bool parkable = (jpark >= 0);

    // Q fragment: lane holds q[hl*4 .. hl*4+3] (duplicated across halves)
    const float* qrow = q + (((size_t)b * LL + l) * HH + h) * EE;
    const float4 q4 = reinterpret_cast<const float4*>(qrow)[hl];

    const float* kbase = k + ((size_t)b * SS * HH + h) * EE;
    const float* vbase = v + ((size_t)b * SS * HH + h) * EE;

    // ---- QK: 11 pair rounds; each LDG.128 fetches two full 256B K rows ----
    float s = -1e30f;
    #pragma unroll
    for (int t = 0; t < 11; t++) {
        const int jv = __shfl_sync(FULL, jpark, 2 * t + half);
        const int jc = max(jv, 0);                        // clamp inactive -> row 0
        const float4 k4 = reinterpret_cast<const float4*>(
            kbase + (size_t)jc * ROW_STRIDE)[hl];
        float partial = q4.x * k4.x;
        partial = fmaf(q4.y, k4.y, partial);
        partial = fmaf(q4.z, k4.z, partial);
        partial = fmaf(q4.w, k4.w, partial);
        // reduce within each 16-lane half (both columns simultaneously)
        partial += __shfl_xor_sync(FULL, partial, 8);
        partial += __shfl_xor_sync(FULL, partial, 4);
        partial += __shfl_xor_sync(FULL, partial, 2);
        partial += __shfl_xor_sync(FULL, partial, 1);
        const float other = __shfl_xor_sync(FULL, partial, 16);
        const float se = half ? other : partial;          // even column's score
        const float so = half ? partial : other;          // odd  column's score
        if (lane == 2 * t     && parkable) s = se;
        if (lane == 2 * t + 1 && parkable) s = so;
    }

    // ---- warp softmax over 22 slots (scale folded in after max) ----
    float m = s;
    #pragma unroll
    for (int off = 16; off; off >>= 1)
        m = fmaxf(m, __shfl_xor_sync(FULL, m, off));
    float p = __expf((s - m) * 0.125f);    // 1/sqrt(E); inactive -> exactly 0
    float denom = p;
    #pragma unroll
    for (int off = 16; off; off >>= 1)
        denom += __shfl_xor_sync(FULL, denom, off);
    p = __fdividef(p, denom);

    // ---- AV: pair pattern, branch-free ----
    float4 acc = make_float4(0.0f, 0.0f, 0.0f, 0.0f);
    #pragma unroll
    for (int t = 0; t < 11; t++) {
        const float pc = __shfl_sync(FULL, p, 2 * t + half);
        const int   jv = __shfl_sync(FULL, jpark, 2 * t + half);
        const int   jc = max(jv, 0);                 // pc==0 annihilates clamped rows
        const float4 v4 = reinterpret_cast<const float4*>(
            vbase + (size_t)jc * ROW_STRIDE)[hl];
        acc.x = fmaf(pc, v4.x, acc.x);
        acc.y = fmaf(pc, v4.y, acc.y);
        acc.z = fmaf(pc, v4.z, acc.z);
        acc.w = fmaf(pc, v4.w, acc.w);
    }
    // fold the two halves
    acc.x += __shfl_xor_sync(FULL, acc.x, 16);
    acc.y += __shfl_xor_sync(FULL, acc.y, 16);
    acc.z += __shfl_xor_sync(FULL, acc.z, 16);
    acc.w += __shfl_xor_sync(FULL, acc.w, 16);

    if (half == 0) {
        float4* orow = reinterpret_cast<float4*>(
            out + (((size_t)b * LL + l) * HH + h) * DD);
        orow[hl] = acc;
    }
}

extern "C" void kernel_launch(void* const* d_in, const int* in_sizes, int n_in,
                              void* d_out, int out_size)
{
    const float* q = (const float*)d_in[0];
    const float* k = (const float*)d_in[1];
    const float* v = (const float*)d_in[2];
    float* out = (float*)d_out;

    const int total_rows = BB * HH * LL;                   // 32768 warps
    const int blocks = total_rows / WARPS_PER_BLOCK;       // 4096
    logsparse_attn_kernel<<<blocks, WARPS_PER_BLOCK * 32>>>(q, k, v, out);
}